// round 4
// baseline (speedup 1.0000x reference)
#include <cuda_runtime.h>
#include <math.h>
#include <stdint.h>

#define B_ 64
#define T_ 512
#define H_ 1024
#define C_ 21

// ================= GEMM: emissions = hs @ W + b =================
// 152 persistent blocks, 8 warps (256 thr).
// Half-warp class split: lanes 0-15 -> classes 0-11, lanes 16-31 -> classes
// 12-23 (cols 21-23 zero-padded). Each lane computes 4 rows (RPT=4).
// Per hh: W = 3 LDS.128 (two 16B addrs/instr -> ~1 wf each), x = 4 broadcast-
// pair LDS -> 7 shared wavefronts per 24 f32x2 FMAs (was 22 wf / 11 FMA).
// Double-buffered chunk staging hides LDG latency. Swizzled tiles (no pad).

#define GEMM_GRID 152
#define GNT 256                     // threads
#define NWARP 8
#define RPT 4
#define GROUP_ROWS 64               // 16 row-slots * RPT
#define NGROUPS ((B_ * T_) / GROUP_ROWS)   // 512
#define WPAD 24
#define NCHUNK 4                    // h-chunks of 32 per warp (H/(8*32))
#define TWORDS 2048                 // 64 rows * 32 cols per warp per buffer

__device__ __forceinline__ unsigned long long pk2(float lo, float hi) {
    unsigned long long r;
    asm("mov.b64 %0, {%1, %2};" : "=l"(r) : "f"(lo), "f"(hi));
    return r;
}
__device__ __forceinline__ void upk2(unsigned long long v, float& lo, float& hi) {
    asm("mov.b64 {%0, %1}, %2;" : "=f"(lo), "=f"(hi) : "l"(v));
}
__device__ __forceinline__ unsigned long long fma2(unsigned long long a,
                                                   unsigned long long b,
                                                   unsigned long long c) {
    unsigned long long d;
    asm("fma.rn.f32x2 %0, %1, %2, %3;" : "=l"(d) : "l"(a), "l"(b), "l"(c));
    return d;
}

__global__ void __launch_bounds__(GNT, 1)
gemm_kernel(const float* __restrict__ hs, const float* __restrict__ W,
            const float* __restrict__ bias, float* __restrict__ out)
{
    extern __shared__ float smem[];
    float* sW    = smem;                       // 1024*24 = 24576 fl (96 KB)
    float* sTA   = sW + H_ * WPAD;             // 8*2048 fl (64 KB), buffer A
    float* sTB   = sTA + NWARP * TWORDS;       // 8*2048 fl (64 KB), buffer B

    // Load W (pad cols 21..23 with zeros)
    for (int idx = threadIdx.x; idx < H_ * WPAD; idx += GNT) {
        int h = idx / WPAD;
        int j = idx - h * WPAD;
        sW[idx] = (j < C_) ? W[h * C_ + j] : 0.f;
    }
    __syncthreads();

    const int warp  = threadIdx.x >> 5;
    const int lane  = threadIdx.x & 31;
    const int half  = lane >> 4;        // 0: classes 0-11, 1: classes 12-23
    const int rbase = lane & 15;
    float* tileA = sTA + warp * TWORDS;
    float* tileB = sTB + warp * TWORDS;
    const int hwarp = warp * (NCHUNK * 32);    // warp's h origin

    for (int g = blockIdx.x; g < NGROUPS; g += gridDim.x) {
        const int row0 = g * GROUP_ROWS;
        unsigned long long acc2[RPT][6];
#pragma unroll
        for (int rp = 0; rp < RPT; rp++)
#pragma unroll
            for (int p = 0; p < 6; p++) acc2[rp][p] = 0ull;

        // stage chunk 0 into A
        {
            const float* src = hs + (size_t)row0 * H_ + hwarp + lane;
#pragma unroll 16
            for (int r = 0; r < GROUP_ROWS; r++)
                tileA[r * 32 + (lane ^ (r & 31))] = src[(size_t)r * H_];
        }
        __syncwarp();

#pragma unroll
        for (int ch = 0; ch < NCHUNK; ch++) {
            float* cur = (ch & 1) ? tileB : tileA;
            float* nxt = (ch & 1) ? tileA : tileB;
            // prefetch-stage next chunk into the other buffer
            if (ch < NCHUNK - 1) {
                const float* src = hs + (size_t)row0 * H_ + hwarp + (ch + 1) * 32 + lane;
#pragma unroll 16
                for (int r = 0; r < GROUP_ROWS; r++)
                    nxt[r * 32 + (lane ^ (r & 31))] = src[(size_t)r * H_];
            }
            const int hbase = hwarp + ch * 32;
#pragma unroll 2
            for (int hh = 0; hh < 32; hh++) {
                const float* wr = sW + (hbase + hh) * WPAD + half * 12;
                const ulonglong2 qa = *(const ulonglong2*)(wr);
                const ulonglong2 qb = *(const ulonglong2*)(wr + 4);
                const ulonglong2 qc = *(const ulonglong2*)(wr + 8);
                const int sx0 = hh ^ rbase;
                const int sx1 = sx0 ^ 16;
                const float x0 = cur[(rbase)      * 32 + sx0];
                const float x1 = cur[(rbase + 16) * 32 + sx1];
                const float x2 = cur[(rbase + 32) * 32 + sx0];
                const float x3 = cur[(rbase + 48) * 32 + sx1];
                const unsigned long long xx0 = pk2(x0, x0);
                const unsigned long long xx1 = pk2(x1, x1);
                const unsigned long long xx2 = pk2(x2, x2);
                const unsigned long long xx3 = pk2(x3, x3);
                acc2[0][0] = fma2(xx0, qa.x, acc2[0][0]);
                acc2[1][0] = fma2(xx1, qa.x, acc2[1][0]);
                acc2[2][0] = fma2(xx2, qa.x, acc2[2][0]);
                acc2[3][0] = fma2(xx3, qa.x, acc2[3][0]);
                acc2[0][1] = fma2(xx0, qa.y, acc2[0][1]);
                acc2[1][1] = fma2(xx1, qa.y, acc2[1][1]);
                acc2[2][1] = fma2(xx2, qa.y, acc2[2][1]);
                acc2[3][1] = fma2(xx3, qa.y, acc2[3][1]);
                acc2[0][2] = fma2(xx0, qb.x, acc2[0][2]);
                acc2[1][2] = fma2(xx1, qb.x, acc2[1][2]);
                acc2[2][2] = fma2(xx2, qb.x, acc2[2][2]);
                acc2[3][2] = fma2(xx3, qb.x, acc2[3][2]);
                acc2[0][3] = fma2(xx0, qb.y, acc2[0][3]);
                acc2[1][3] = fma2(xx1, qb.y, acc2[1][3]);
                acc2[2][3] = fma2(xx2, qb.y, acc2[2][3]);
                acc2[3][3] = fma2(xx3, qb.y, acc2[3][3]);
                acc2[0][4] = fma2(xx0, qc.x, acc2[0][4]);
                acc2[1][4] = fma2(xx1, qc.x, acc2[1][4]);
                acc2[2][4] = fma2(xx2, qc.x, acc2[2][4]);
                acc2[3][4] = fma2(xx3, qc.x, acc2[3][4]);
                acc2[0][5] = fma2(xx0, qc.y, acc2[0][5]);
                acc2[1][5] = fma2(xx1, qc.y, acc2[1][5]);
                acc2[2][5] = fma2(xx2, qc.y, acc2[2][5]);
                acc2[3][5] = fma2(xx3, qc.y, acc2[3][5]);
            }
            __syncwarp();
        }

        // all warps done consuming tiles -> reuse buffer-A region as reduction
        __syncthreads();
        {
            float* red = sTA + warp * (GROUP_ROWS * C_);   // 1344 fl per warp
#pragma unroll
            for (int rp = 0; rp < RPT; rp++) {
                const int row = rbase + 16 * rp;
                float* dst = red + row * C_;
#pragma unroll
                for (int p = 0; p < 6; p++) {
                    float lo_, hi_;
                    upk2(acc2[rp][p], lo_, hi_);
                    const int c0 = half * 12 + 2 * p;
                    if (c0 < C_)     dst[c0] = lo_;
                    if (c0 + 1 < C_) dst[c0 + 1] = hi_;
                }
            }
        }
        __syncthreads();

        // combine across 8 warps + bias, coalesced store
        const int NOUT = GROUP_ROWS * C_;                 // 1344
        for (int idx = threadIdx.x; idx < NOUT; idx += GNT) {
            float s = 0.f;
#pragma unroll
            for (int w2 = 0; w2 < NWARP; w2++) s += sTA[w2 * NOUT + idx];
            out[(size_t)row0 * C_ + idx] = s + bias[idx % C_];
        }
        __syncthreads();
    }
}

// ============ CRF: per-sequence forward in exp space ============
// One block per sequence, 128 threads. Bulk-stage exp(emissions) to shared.
// Warp 0 runs the recursion unrolled x8 (renorm folded into step 8, no
// per-iteration branch); warp 1 computes the numerator.

__device__ float g_llh[B_];

__global__ void __launch_bounds__(128, 1)
crf_kernel(const float* __restrict__ em_all, const float* __restrict__ trans,
           const float* __restrict__ startT, const float* __restrict__ endT,
           const int* __restrict__ att, const int* __restrict__ labels)
{
    __shared__ __align__(16) float sEexp[T_ * C_];   // 43008 B
    __shared__ __align__(16) float sV[2][24];
    __shared__ float sNum;

    const int b = blockIdx.x;
    const int tid = threadIdx.x;
    const int warp = tid >> 5;
    const int lane = tid & 31;
    const float* em = em_all + (size_t)b * T_ * C_;
    const int* tag = labels + b * T_;
    const int* mrow = att + b * T_;
    const unsigned FULL = 0xffffffffu;

    // Bulk-stage exp(em) (float4, coalesced)
    {
        const float4* em4 = (const float4*)em;
        float4* se4 = (float4*)sEexp;
        const int n4 = (T_ * C_) / 4;                  // 2688
        for (int i = tid; i < n4; i += 128) {
            float4 v = em4[i];
            v.x = __expf(v.x); v.y = __expf(v.y);
            v.z = __expf(v.z); v.w = __expf(v.w);
            se4[i] = v;
        }
    }
    __syncthreads();

    // sequence length L (mask is a true prefix)
    int L = 0;
    if (warp < 2) {
        int cnt = 0;
        for (int t = lane; t < T_; t += 32) {
            bool mk = (t == 0) ? true : (mrow[t] != 0 && tag[t] != -100);
            cnt += mk ? 1 : 0;
        }
#pragma unroll
        for (int o = 16; o; o >>= 1) cnt += __shfl_xor_sync(FULL, cnt, o);
        L = cnt;
    }

    if (warp == 1) {
        float part = 0.f;
        for (int t = 1 + lane; t < L; t += 32) {
            part += trans[tag[t - 1] * C_ + tag[t]] + em[t * C_ + tag[t]];
        }
#pragma unroll
        for (int o = 16; o; o >>= 1) part += __shfl_xor_sync(FULL, part, o);
        if (lane == 0)
            sNum = part + startT[tag[0]] + em[tag[0]] + endT[tag[L - 1]];
    }

    float logZ = 0.f;
    if (warp == 0) {
        const bool act = (lane < C_);
        const int j = act ? lane : 0;

        float Ej[C_];
#pragma unroll
        for (int i = 0; i < C_; i++) Ej[i] = __expf(trans[i * C_ + j]);
        const float eend = __expf(endT[j]);

        float w = __expf(startT[j]) * sEexp[j];
        float w0 = __shfl_sync(FULL, w, 0);
        float acc = __logf(w0);
        float rw0 = __fdividef(1.f, w0);
        if (lane < 24) sV[0][lane] = w * rw0;
        __syncwarp();

#define CRF_STEP(SRC, DST, TIDX, RENORM) do {                                  \
        const float4 p0 = *(const float4*)&sV[SRC][0];                         \
        const float4 p1 = *(const float4*)&sV[SRC][4];                         \
        const float4 p2 = *(const float4*)&sV[SRC][8];                         \
        const float4 p3 = *(const float4*)&sV[SRC][12];                        \
        const float4 p4 = *(const float4*)&sV[SRC][16];                        \
        const float  p5 = sV[SRC][20];                                         \
        const float eet = sEexp[(TIDX) * C_ + j];                              \
        float s0 = Ej[0]*p0.x, s1 = Ej[1]*p0.y, s2 = Ej[2]*p0.z;               \
        float s3 = Ej[3]*p0.w, s4 = Ej[4]*p1.x, s5 = Ej[5]*p1.y;               \
        float s6 = Ej[6]*p1.z;                                                 \
        s0 = fmaf(Ej[7],  p1.w, s0); s1 = fmaf(Ej[8],  p2.x, s1);              \
        s2 = fmaf(Ej[9],  p2.y, s2); s3 = fmaf(Ej[10], p2.z, s3);              \
        s4 = fmaf(Ej[11], p2.w, s4); s5 = fmaf(Ej[12], p3.x, s5);              \
        s6 = fmaf(Ej[13], p3.y, s6);                                           \
        s0 = fmaf(Ej[14], p3.z, s0); s1 = fmaf(Ej[15], p3.w, s1);              \
        s2 = fmaf(Ej[16], p4.x, s2); s3 = fmaf(Ej[17], p4.y, s3);              \
        s4 = fmaf(Ej[18], p4.z, s4); s5 = fmaf(Ej[19], p4.w, s5);              \
        s6 = fmaf(Ej[20], p5,   s6);                                           \
        float u = (((s0 + s1) + (s2 + s3)) + ((s4 + s5) + s6)) * eet;          \
        if (RENORM) {                                                          \
            float cn = __shfl_sync(FULL, u, 0);                                \
            acc += __logf(cn);                                                 \
            u *= __fdividef(1.f, cn);                                          \
        }                                                                      \
        if (lane < 24) sV[DST][lane] = u;                                      \
        __syncwarp();                                                          \
    } while (0)

        int t = 1;
        const int nFull = (L - 1) >> 3;
        for (int it = 0; it < nFull; it++) {
            CRF_STEP(0, 1, t + 0, 0);
            CRF_STEP(1, 0, t + 1, 0);
            CRF_STEP(0, 1, t + 2, 0);
            CRF_STEP(1, 0, t + 3, 0);
            CRF_STEP(0, 1, t + 4, 0);
            CRF_STEP(1, 0, t + 5, 0);
            CRF_STEP(0, 1, t + 6, 0);
            CRF_STEP(1, 0, t + 7, 1);   // renorm folded in
            t += 8;
        }
        int buf = 0;
        for (; t < L; t++) {
            if (buf == 0) CRF_STEP(0, 1, t, 0);
            else          CRF_STEP(1, 0, t, 0);
            buf ^= 1;
        }

        float vf = act ? sV[buf][lane] : 0.f;
        float z = vf * eend;
#pragma unroll
        for (int o = 16; o; o >>= 1) z += __shfl_xor_sync(FULL, z, o);
        logZ = acc + __logf(z);
    }

    __syncthreads();
    if (tid == 0) g_llh[b] = sNum - logZ;
}

__global__ void reduce_kernel(float* __restrict__ out_loss)
{
    const int lane = threadIdx.x;   // 64 threads
    __shared__ float sp[2];
    float v = g_llh[lane];
#pragma unroll
    for (int o = 16; o; o >>= 1) v += __shfl_xor_sync(0xffffffffu, v, o);
    if ((lane & 31) == 0) sp[lane >> 5] = v;
    __syncthreads();
    if (lane == 0) out_loss[0] = -(sp[0] + sp[1]) / (float)B_;
}

// ---------------- launch ----------------

extern "C" void kernel_launch(void* const* d_in, const int* in_sizes, int n_in,
                              void* d_out, int out_size)
{
    const float* hs     = (const float*)d_in[0];
    const float* W      = (const float*)d_in[1];
    const float* bias   = (const float*)d_in[2];
    const float* trans  = (const float*)d_in[3];
    const float* startT = (const float*)d_in[4];
    const float* endT   = (const float*)d_in[5];
    const int*   att    = (const int*)d_in[6];
    const int*   labels = (const int*)d_in[7];
    float* out = (float*)d_out;

    const size_t smem = (size_t)(H_ * WPAD + 2 * NWARP * TWORDS) * sizeof(float);
    cudaFuncSetAttribute(gemm_kernel, cudaFuncAttributeMaxDynamicSharedMemorySize, (int)smem);

    gemm_kernel<<<GEMM_GRID, GNT, smem>>>(hs, W, bias, out);
    crf_kernel<<<B_, 128>>>(out, trans, startT, endT, att, labels);
    reduce_kernel<<<1, 64>>>(out + (out_size - 1));
}

// round 5
// speedup vs baseline: 1.2650x; 1.2650x over previous
#include <cuda_runtime.h>
#include <math.h>
#include <stdint.h>

#define B_ 64
#define T_ 512
#define H_ 1024
#define C_ 21

// ================= GEMM: emissions = hs @ W + b =================
// 152 persistent blocks, 32 warps (1024 thr), 1 CTA/SM, occ 50%.
// Warp w owns h-slice [w*32, w*32+32). Group = 32 rows.
// Half-warp class split: lanes 0-15 -> classes 0-11, lanes 16-31 -> 12-23
// (cols 21-23 zero-padded); each lane computes 2 rows (rbase, rbase+16).
// Per hh: 3 LDS.128 (W, 2 distinct 16B addrs -> 1 wf each) + 2 broadcast-
// dedup x reads -> ~5 wf per 12 f32x2 FMAs. Cross-warp combine in shared.

#define GEMM_GRID 152
#define GNT 1024
#define NWARP 32
#define GROUP_ROWS 32
#define NGROUPS ((B_ * T_) / GROUP_ROWS)   // 1024
#define WPAD 24
#define STRIDE_W 1024                      // per-warp staging stride (floats)

__device__ __forceinline__ unsigned long long pk2(float lo, float hi) {
    unsigned long long r;
    asm("mov.b64 %0, {%1, %2};" : "=l"(r) : "f"(lo), "f"(hi));
    return r;
}
__device__ __forceinline__ void upk2(unsigned long long v, float& lo, float& hi) {
    asm("mov.b64 {%0, %1}, %2;" : "=f"(lo), "=f"(hi) : "l"(v));
}
__device__ __forceinline__ unsigned long long fma2(unsigned long long a,
                                                   unsigned long long b,
                                                   unsigned long long c) {
    unsigned long long d;
    asm("fma.rn.f32x2 %0, %1, %2, %3;" : "=l"(d) : "l"(a), "l"(b), "l"(c));
    return d;
}

__global__ void __launch_bounds__(GNT, 1)
gemm_kernel(const float* __restrict__ hs, const float* __restrict__ W,
            const float* __restrict__ bias, float* __restrict__ out)
{
    extern __shared__ float smem[];
    float* sW     = smem;                    // 1024*24 = 24576 fl (96 KB)
    float* sStage = sW + H_ * WPAD;          // 32*1024 fl (128 KB)

    // Load W (pad cols 21..23 with zeros)
    for (int idx = threadIdx.x; idx < H_ * WPAD; idx += GNT) {
        int h = idx / WPAD;
        int j = idx - h * WPAD;
        sW[idx] = (j < C_) ? W[h * C_ + j] : 0.f;
    }
    __syncthreads();

    const int warp  = threadIdx.x >> 5;
    const int lane  = threadIdx.x & 31;
    const int half  = lane >> 4;
    const int rbase = lane & 15;
    float* tile = sStage + warp * STRIDE_W;
    const int hwarp = warp * 32;

    for (int g = blockIdx.x; g < NGROUPS; g += GEMM_GRID) {
        const int row0 = g * GROUP_ROWS;

        // stage 32 rows x 32 h (coalesced per row, xor swizzle)
        {
            const float* src = hs + (size_t)row0 * H_ + hwarp + lane;
#pragma unroll 8
            for (int r = 0; r < GROUP_ROWS; r++)
                tile[r * 32 + (lane ^ r)] = src[(size_t)r * H_];
        }
        __syncwarp();

        unsigned long long acc2[2][6];
#pragma unroll
        for (int rp = 0; rp < 2; rp++)
#pragma unroll
            for (int p = 0; p < 6; p++) acc2[rp][p] = 0ull;

#pragma unroll 8
        for (int hh = 0; hh < 32; hh++) {
            const float* wr = sW + (hwarp + hh) * WPAD + half * 12;
            const ulonglong2 qa = *(const ulonglong2*)(wr);
            const ulonglong2 qb = *(const ulonglong2*)(wr + 4);
            const ulonglong2 qc = *(const ulonglong2*)(wr + 8);
            const float x0 = tile[rbase * 32 + (hh ^ rbase)];
            const float x1 = tile[(rbase + 16) * 32 + (hh ^ rbase ^ 16)];
            const unsigned long long xx0 = pk2(x0, x0);
            const unsigned long long xx1 = pk2(x1, x1);
            acc2[0][0] = fma2(xx0, qa.x, acc2[0][0]);
            acc2[1][0] = fma2(xx1, qa.x, acc2[1][0]);
            acc2[0][1] = fma2(xx0, qa.y, acc2[0][1]);
            acc2[1][1] = fma2(xx1, qa.y, acc2[1][1]);
            acc2[0][2] = fma2(xx0, qb.x, acc2[0][2]);
            acc2[1][2] = fma2(xx1, qb.x, acc2[1][2]);
            acc2[0][3] = fma2(xx0, qb.y, acc2[0][3]);
            acc2[1][3] = fma2(xx1, qb.y, acc2[1][3]);
            acc2[0][4] = fma2(xx0, qc.x, acc2[0][4]);
            acc2[1][4] = fma2(xx1, qc.x, acc2[1][4]);
            acc2[0][5] = fma2(xx0, qc.y, acc2[0][5]);
            acc2[1][5] = fma2(xx1, qc.y, acc2[1][5]);
        }
        __syncwarp();   // this warp done reading its tile

        // write partials over own tile area (672 floats used of 1024)
        {
            float* red = tile;
#pragma unroll
            for (int rp = 0; rp < 2; rp++) {
                const int row = rbase + 16 * rp;
                float* dst = red + row * C_;
#pragma unroll
                for (int p = 0; p < 6; p++) {
                    float lo_, hi_;
                    upk2(acc2[rp][p], lo_, hi_);
                    const int c0 = half * 12 + 2 * p;
                    if (c0 < C_)     dst[c0]     = lo_;
                    if (c0 + 1 < C_) dst[c0 + 1] = hi_;
                }
            }
        }
        __syncthreads();

        // combine across 32 warps + bias, coalesced store
        const int NOUT = GROUP_ROWS * C_;   // 672
        if (threadIdx.x < NOUT) {
            const int idx = threadIdx.x;
            float s = 0.f;
#pragma unroll
            for (int w2 = 0; w2 < NWARP; w2++) s += sStage[w2 * STRIDE_W + idx];
            out[(size_t)row0 * C_ + idx] = s + bias[idx % C_];
        }
        __syncthreads();
    }
}

// ============ CRF: per-sequence forward, registers-only ============
// One block per sequence, 128 threads. Bulk-stage exp(emissions) to shared.
// Warp 0: recursion with v replicated in registers; per step a 21-fma tree
// produces u_j on lane j, then 21 shfl all-gather rebuilds v. No shared
// traffic or warp sync in the serial chain. Warp 1: numerator.

__device__ float g_llh[B_];

__global__ void __launch_bounds__(128, 1)
crf_kernel(const float* __restrict__ em_all, const float* __restrict__ trans,
           const float* __restrict__ startT, const float* __restrict__ endT,
           const int* __restrict__ att, const int* __restrict__ labels)
{
    __shared__ __align__(16) float sEexp[T_ * C_];   // 43008 B
    __shared__ float sNum;

    const int b = blockIdx.x;
    const int tid = threadIdx.x;
    const int warp = tid >> 5;
    const int lane = tid & 31;
    const float* em = em_all + (size_t)b * T_ * C_;
    const int* tag = labels + b * T_;
    const int* mrow = att + b * T_;
    const unsigned FULL = 0xffffffffu;

    // Bulk-stage exp(em)
    {
        const float4* em4 = (const float4*)em;
        float4* se4 = (float4*)sEexp;
        const int n4 = (T_ * C_) / 4;                  // 2688
        for (int i = tid; i < n4; i += 128) {
            float4 v = em4[i];
            v.x = __expf(v.x); v.y = __expf(v.y);
            v.z = __expf(v.z); v.w = __expf(v.w);
            se4[i] = v;
        }
    }
    __syncthreads();

    // sequence length L (mask is a true prefix)
    int L = 0;
    if (warp < 2) {
        int cnt = 0;
        for (int t = lane; t < T_; t += 32) {
            bool mk = (t == 0) ? true : (mrow[t] != 0 && tag[t] != -100);
            cnt += mk ? 1 : 0;
        }
#pragma unroll
        for (int o = 16; o; o >>= 1) cnt += __shfl_xor_sync(FULL, cnt, o);
        L = cnt;
    }

    if (warp == 1) {
        float part = 0.f;
        for (int t = 1 + lane; t < L; t += 32) {
            part += trans[tag[t - 1] * C_ + tag[t]] + em[t * C_ + tag[t]];
        }
#pragma unroll
        for (int o = 16; o; o >>= 1) part += __shfl_xor_sync(FULL, part, o);
        if (lane == 0)
            sNum = part + startT[tag[0]] + em[tag[0]] + endT[tag[L - 1]];
    }

    float logZ = 0.f;
    if (warp == 0) {
        const int j = (lane < C_) ? lane : (C_ - 1);   // clamp (no OOB)

        float Ej[C_];
#pragma unroll
        for (int i = 0; i < C_; i++) Ej[i] = __expf(trans[i * C_ + j]);
        const float eend = (lane < C_) ? __expf(endT[j]) : 0.f;

        // init: w_j = exp(start_j + em0_j), replicate, normalize by w_0
        float w = __expf(startT[j]) * sEexp[j];
        float v[C_];
#pragma unroll
        for (int i = 0; i < C_; i++) v[i] = __shfl_sync(FULL, w, i);
        float acc = __logf(v[0]);
        const float rv0 = __fdividef(1.f, v[0]);
#pragma unroll
        for (int i = 0; i < C_; i++) v[i] *= rv0;

#define CRF_STEP(TIDX, RENORM) do {                                           \
        const float eet = sEexp[(TIDX) * C_ + j];                             \
        float s0 = Ej[0]*v[0], s1 = Ej[1]*v[1], s2 = Ej[2]*v[2];              \
        float s3 = Ej[3]*v[3], s4 = Ej[4]*v[4], s5 = Ej[5]*v[5];              \
        float s6 = Ej[6]*v[6];                                                \
        s0 = fmaf(Ej[7],  v[7],  s0); s1 = fmaf(Ej[8],  v[8],  s1);           \
        s2 = fmaf(Ej[9],  v[9],  s2); s3 = fmaf(Ej[10], v[10], s3);           \
        s4 = fmaf(Ej[11], v[11], s4); s5 = fmaf(Ej[12], v[12], s5);           \
        s6 = fmaf(Ej[13], v[13], s6);                                         \
        s0 = fmaf(Ej[14], v[14], s0); s1 = fmaf(Ej[15], v[15], s1);           \
        s2 = fmaf(Ej[16], v[16], s2); s3 = fmaf(Ej[17], v[17], s3);           \
        s4 = fmaf(Ej[18], v[18], s4); s5 = fmaf(Ej[19], v[19], s5);           \
        s6 = fmaf(Ej[20], v[20], s6);                                         \
        float u = (((s0 + s1) + (s2 + s3)) + ((s4 + s5) + s6)) * eet;         \
        if (RENORM) {                                                         \
            float cn = __shfl_sync(FULL, u, 0);                               \
            acc += __logf(cn);                                                \
            u *= __fdividef(1.f, cn);                                         \
        }                                                                     \
        _Pragma("unroll")                                                     \
        for (int i = 0; i < C_; i++) v[i] = __shfl_sync(FULL, u, i);          \
    } while (0)

        int t = 1;
        const int nFull = (L - 1) >> 3;
        for (int it = 0; it < nFull; it++) {
            CRF_STEP(t + 0, 0);
            CRF_STEP(t + 1, 0);
            CRF_STEP(t + 2, 0);
            CRF_STEP(t + 3, 0);
            CRF_STEP(t + 4, 0);
            CRF_STEP(t + 5, 0);
            CRF_STEP(t + 6, 0);
            CRF_STEP(t + 7, 1);   // renorm folded in
            t += 8;
        }
        for (; t < L; t++) {
            CRF_STEP(t, 0);
        }

        // z = sum_j v_j * exp(end_j): lane j contributes its own column
        float z = v[j] * eend;    // eend=0 for lanes >= C_
#pragma unroll
        for (int o = 16; o; o >>= 1) z += __shfl_xor_sync(FULL, z, o);
        logZ = acc + __logf(z);
    }

    __syncthreads();
    if (tid == 0) g_llh[b] = sNum - logZ;
}

__global__ void reduce_kernel(float* __restrict__ out_loss)
{
    const int lane = threadIdx.x;   // 64 threads
    __shared__ float sp[2];
    float v = g_llh[lane];
#pragma unroll
    for (int o = 16; o; o >>= 1) v += __shfl_xor_sync(0xffffffffu, v, o);
    if ((lane & 31) == 0) sp[lane >> 5] = v;
    __syncthreads();
    if (lane == 0) out_loss[0] = -(sp[0] + sp[1]) / (float)B_;
}

// ---------------- launch ----------------

extern "C" void kernel_launch(void* const* d_in, const int* in_sizes, int n_in,
                              void* d_out, int out_size)
{
    const float* hs     = (const float*)d_in[0];
    const float* W      = (const float*)d_in[1];
    const float* bias   = (const float*)d_in[2];
    const float* trans  = (const float*)d_in[3];
    const float* startT = (const float*)d_in[4];
    const float* endT   = (const float*)d_in[5];
    const int*   att    = (const int*)d_in[6];
    const int*   labels = (const int*)d_in[7];
    float* out = (float*)d_out;

    const size_t smem = (size_t)(H_ * WPAD + NWARP * STRIDE_W) * sizeof(float);
    cudaFuncSetAttribute(gemm_kernel, cudaFuncAttributeMaxDynamicSharedMemorySize, (int)smem);

    gemm_kernel<<<GEMM_GRID, GNT, smem>>>(hs, W, bias, out);
    crf_kernel<<<B_, 128>>>(out, trans, startT, endT, att, labels);
    reduce_kernel<<<1, 64>>>(out + (out_size - 1));
}

// round 6
// speedup vs baseline: 1.2962x; 1.0247x over previous
#include <cuda_runtime.h>
#include <math.h>
#include <stdint.h>

#define B_ 64
#define T_ 512
#define H_ 1024
#define C_ 21

// ================= GEMM: emissions = hs @ W + b =================
// 152 persistent blocks, 32 warps (1024 thr), 1 CTA/SM.
// Warp w owns h-slice [w*32, w*32+32). Group = 32 rows.
// Transposed PAIR tile: word (2*rbase)^(hh&30) of hh-row holds x[rbase][hh],
// next word holds x[rbase+16][hh] -> ONE LDS.64 per hh feeds both rows.
// Half-warp class split (lanes 0-15: classes 0-11, 16-31: 12-23 zero-padded).
// Per hh: 3 LDS.128 (W, immediate offsets) + 1 LDS.64 (x, prefetched) +
// 2 pk2 + 12 f32x2 FMA.

#define GEMM_GRID 152
#define GNT 1024
#define NWARP 32
#define GROUP_ROWS 32
#define NGROUPS ((B_ * T_) / GROUP_ROWS)   // 1024
#define WPAD 24
#define STRIDE_W 1024

__device__ __forceinline__ unsigned long long pk2(float lo, float hi) {
    unsigned long long r;
    asm("mov.b64 %0, {%1, %2};" : "=l"(r) : "f"(lo), "f"(hi));
    return r;
}
__device__ __forceinline__ void upk2(unsigned long long v, float& lo, float& hi) {
    asm("mov.b64 {%0, %1}, %2;" : "=f"(lo), "=f"(hi) : "l"(v));
}
__device__ __forceinline__ unsigned long long fma2(unsigned long long a,
                                                   unsigned long long b,
                                                   unsigned long long c) {
    unsigned long long d;
    asm("fma.rn.f32x2 %0, %1, %2, %3;" : "=l"(d) : "l"(a), "l"(b), "l"(c));
    return d;
}
__device__ __forceinline__ unsigned long long mul2(unsigned long long a,
                                                   unsigned long long b) {
    unsigned long long d;
    asm("mul.rn.f32x2 %0, %1, %2;" : "=l"(d) : "l"(a), "l"(b));
    return d;
}
__device__ __forceinline__ unsigned long long add2(unsigned long long a,
                                                   unsigned long long b) {
    unsigned long long d;
    asm("add.rn.f32x2 %0, %1, %2;" : "=l"(d) : "l"(a), "l"(b));
    return d;
}

__global__ void __launch_bounds__(GNT, 1)
gemm_kernel(const float* __restrict__ hs, const float* __restrict__ W,
            const float* __restrict__ bias, float* __restrict__ out)
{
    extern __shared__ float smem[];
    float* sW     = smem;                    // 1024*24 fl (96 KB)
    float* sStage = sW + H_ * WPAD;          // 32*1024 fl (128 KB)

    for (int idx = threadIdx.x; idx < H_ * WPAD; idx += GNT) {
        int h = idx / WPAD;
        int j = idx - h * WPAD;
        sW[idx] = (j < C_) ? W[h * C_ + j] : 0.f;
    }
    __syncthreads();

    const int warp  = threadIdx.x >> 5;
    const int lane  = threadIdx.x & 31;
    const int half  = lane >> 4;
    const int rbase = lane & 15;
    const int wxor  = lane & 30;            // staging write swizzle
    float* tile = sStage + warp * STRIDE_W;
    const int hwarp = warp * 32;
    const float* wbase = sW + hwarp * WPAD + half * 12;

    for (int g = blockIdx.x; g < NGROUPS; g += GEMM_GRID) {
        const int row0 = g * GROUP_ROWS;

        // stage: lane = h; row r -> pair column, xor-swizzled (2-way conflict)
        {
            const float* src = hs + (size_t)row0 * H_ + hwarp + lane;
#pragma unroll 8
            for (int r = 0; r < GROUP_ROWS; r++) {
                const int col = ((r & 15) << 1) | (r >> 4);
                tile[(lane << 5) + (col ^ wxor)] = src[(size_t)r * H_];
            }
        }
        __syncwarp();

        unsigned long long acc2[2][6];
#pragma unroll
        for (int rp = 0; rp < 2; rp++)
#pragma unroll
            for (int p = 0; p < 6; p++) acc2[rp][p] = 0ull;

        // x pair prefetch for hh=0 (hh&30 = 0)
        float2 xp = *(const float2*)&tile[(2 * rbase)];
#pragma unroll
        for (int hh = 0; hh < 32; hh++) {
            float2 xq;
            if (hh < 31) {
                xq = *(const float2*)&tile[((hh + 1) << 5) +
                                           ((2 * rbase) ^ ((hh + 1) & 30))];
            }
            const ulonglong2 qa = *(const ulonglong2*)(wbase + hh * WPAD);
            const ulonglong2 qb = *(const ulonglong2*)(wbase + hh * WPAD + 4);
            const ulonglong2 qc = *(const ulonglong2*)(wbase + hh * WPAD + 8);
            const unsigned long long xx0 = pk2(xp.x, xp.x);
            const unsigned long long xx1 = pk2(xp.y, xp.y);
            acc2[0][0] = fma2(xx0, qa.x, acc2[0][0]);
            acc2[1][0] = fma2(xx1, qa.x, acc2[1][0]);
            acc2[0][1] = fma2(xx0, qa.y, acc2[0][1]);
            acc2[1][1] = fma2(xx1, qa.y, acc2[1][1]);
            acc2[0][2] = fma2(xx0, qb.x, acc2[0][2]);
            acc2[1][2] = fma2(xx1, qb.x, acc2[1][2]);
            acc2[0][3] = fma2(xx0, qb.y, acc2[0][3]);
            acc2[1][3] = fma2(xx1, qb.y, acc2[1][3]);
            acc2[0][4] = fma2(xx0, qc.x, acc2[0][4]);
            acc2[1][4] = fma2(xx1, qc.x, acc2[1][4]);
            acc2[0][5] = fma2(xx0, qc.y, acc2[0][5]);
            acc2[1][5] = fma2(xx1, qc.y, acc2[1][5]);
            xp = xq;
        }
        __syncwarp();

        // partials over own tile area
        {
            float* red = tile;
#pragma unroll
            for (int rp = 0; rp < 2; rp++) {
                const int row = rbase + 16 * rp;
                float* dst = red + row * C_;
#pragma unroll
                for (int p = 0; p < 6; p++) {
                    float lo_, hi_;
                    upk2(acc2[rp][p], lo_, hi_);
                    const int c0 = half * 12 + 2 * p;
                    if (c0 < C_)     dst[c0]     = lo_;
                    if (c0 + 1 < C_) dst[c0 + 1] = hi_;
                }
            }
        }
        __syncthreads();

        const int NOUT = GROUP_ROWS * C_;   // 672
        if (threadIdx.x < NOUT) {
            const int idx = threadIdx.x;
            float s = 0.f;
#pragma unroll
            for (int w2 = 0; w2 < NWARP; w2++) s += sStage[w2 * STRIDE_W + idx];
            out[(size_t)row0 * C_ + idx] = s + bias[idx % C_];
        }
        __syncthreads();
    }
}

// ============ CRF: per-sequence forward, packed-f32x2 registers ============
// One block per sequence, 128 threads. L computed first; exp(emissions)
// staged only for t < L. Warp 0: recursion with v held as 11 packed f32x2
// regs (replicated across lanes); per step 11 fma2 + 2 fadd2 tree, then
// 21 shfl + 11 pk2 all-gather. Warp 1: numerator.

__device__ float g_llh[B_];

__global__ void __launch_bounds__(128, 1)
crf_kernel(const float* __restrict__ em_all, const float* __restrict__ trans,
           const float* __restrict__ startT, const float* __restrict__ endT,
           const int* __restrict__ att, const int* __restrict__ labels)
{
    __shared__ __align__(16) float sEexp[T_ * C_];   // 43008 B
    __shared__ float sNum;

    const int b = blockIdx.x;
    const int tid = threadIdx.x;
    const int warp = tid >> 5;
    const int lane = tid & 31;
    const float* em = em_all + (size_t)b * T_ * C_;
    const int* tag = labels + b * T_;
    const int* mrow = att + b * T_;
    const unsigned FULL = 0xffffffffu;

    // L (mask is a true prefix) — all warps compute it (needed for staging bound)
    int cnt = 0;
    for (int t = lane; t < T_; t += 32) {
        bool mk = (t == 0) ? true : (mrow[t] != 0 && tag[t] != -100);
        cnt += mk ? 1 : 0;
    }
#pragma unroll
    for (int o = 16; o; o >>= 1) cnt += __shfl_xor_sync(FULL, cnt, o);
    const int L = cnt;

    // Bulk-stage exp(em) only for t < L
    {
        const float4* em4 = (const float4*)em;
        float4* se4 = (float4*)sEexp;
        const int n4 = (L * C_ + 3) >> 2;
        for (int i = tid; i < n4; i += 128) {
            float4 v = em4[i];
            v.x = __expf(v.x); v.y = __expf(v.y);
            v.z = __expf(v.z); v.w = __expf(v.w);
            se4[i] = v;
        }
    }
    __syncthreads();

    if (warp == 1) {
        float part = 0.f;
        for (int t = 1 + lane; t < L; t += 32) {
            part += trans[tag[t - 1] * C_ + tag[t]] + em[t * C_ + tag[t]];
        }
#pragma unroll
        for (int o = 16; o; o >>= 1) part += __shfl_xor_sync(FULL, part, o);
        if (lane == 0)
            sNum = part + startT[tag[0]] + em[tag[0]] + endT[tag[L - 1]];
    }

    float logZ = 0.f;
    if (warp == 0) {
        const int j = (lane < C_) ? lane : (C_ - 1);

        // packed transition columns: E2[k] = (exp(T[2k][j]), exp(T[2k+1][j]))
        unsigned long long E2[11];
#pragma unroll
        for (int k = 0; k < 10; k++)
            E2[k] = pk2(__expf(trans[(2 * k) * C_ + j]),
                        __expf(trans[(2 * k + 1) * C_ + j]));
        E2[10] = pk2(__expf(trans[20 * C_ + j]), 0.f);
        const float eend = (lane < C_) ? __expf(endT[j]) : 0.f;

        // init: w_j = exp(start_j)*exp(em0_j); gather packed; normalize by w_0
        float w = __expf(startT[j]) * sEexp[j];
        unsigned long long v2[11];
#pragma unroll
        for (int k = 0; k < 10; k++)
            v2[k] = pk2(__shfl_sync(FULL, w, 2 * k),
                        __shfl_sync(FULL, w, 2 * k + 1));
        v2[10] = pk2(__shfl_sync(FULL, w, 20), 0.f);
        float w0 = __shfl_sync(FULL, w, 0);
        float acc = __logf(w0);
        {
            const float rw0 = __fdividef(1.f, w0);
            const unsigned long long rr = pk2(rw0, rw0);
#pragma unroll
            for (int k = 0; k < 11; k++) v2[k] = mul2(v2[k], rr);
        }

#define CRF_STEP(TIDX, RENORM) do {                                          \
        const float eet = sEexp[(TIDX) * C_ + j];                            \
        unsigned long long ch0 = mul2(E2[0], v2[0]);                         \
        unsigned long long ch1 = mul2(E2[1], v2[1]);                         \
        unsigned long long ch2 = mul2(E2[2], v2[2]);                         \
        ch0 = fma2(E2[3], v2[3], ch0);                                       \
        ch1 = fma2(E2[4], v2[4], ch1);                                       \
        ch2 = fma2(E2[5], v2[5], ch2);                                       \
        ch0 = fma2(E2[6], v2[6], ch0);                                       \
        ch1 = fma2(E2[7], v2[7], ch1);                                       \
        ch2 = fma2(E2[8], v2[8], ch2);                                       \
        ch0 = fma2(E2[9], v2[9], ch0);                                       \
        ch1 = fma2(E2[10], v2[10], ch1);                                     \
        unsigned long long s2 = add2(add2(ch0, ch1), ch2);                   \
        float slo, shi; upk2(s2, slo, shi);                                  \
        float u = (slo + shi) * eet;                                         \
        if (RENORM) {                                                        \
            float cn = __shfl_sync(FULL, u, 0);                              \
            acc += __logf(cn);                                               \
            u *= __fdividef(1.f, cn);                                        \
        }                                                                    \
        _Pragma("unroll")                                                    \
        for (int k = 0; k < 10; k++)                                         \
            v2[k] = pk2(__shfl_sync(FULL, u, 2 * k),                         \
                        __shfl_sync(FULL, u, 2 * k + 1));                    \
        v2[10] = pk2(__shfl_sync(FULL, u, 20), 0.f);                         \
    } while (0)

        int t = 1;
        const int nFull = (L - 1) >> 3;
        for (int it = 0; it < nFull; it++) {
            CRF_STEP(t + 0, 0);
            CRF_STEP(t + 1, 0);
            CRF_STEP(t + 2, 0);
            CRF_STEP(t + 3, 0);
            CRF_STEP(t + 4, 0);
            CRF_STEP(t + 5, 0);
            CRF_STEP(t + 6, 0);
            CRF_STEP(t + 7, 1);   // renorm folded in
            t += 8;
        }
        for (; t < L; t++) {
            CRF_STEP(t, 0);
        }

        // z = sum_j v_j * exp(end_j); lane j extracts its own component
        float vlo, vhi;
        upk2(v2[j >> 1], vlo, vhi);
        float vf = (j & 1) ? vhi : vlo;
        float z = vf * eend;          // 0 on lanes >= C_
#pragma unroll
        for (int o = 16; o; o >>= 1) z += __shfl_xor_sync(FULL, z, o);
        logZ = acc + __logf(z);
    }

    __syncthreads();
    if (tid == 0) g_llh[b] = sNum - logZ;
}

__global__ void reduce_kernel(float* __restrict__ out_loss)
{
    const int lane = threadIdx.x;   // 64 threads
    __shared__ float sp[2];
    float v = g_llh[lane];
#pragma unroll
    for (int o = 16; o; o >>= 1) v += __shfl_xor_sync(0xffffffffu, v, o);
    if ((lane & 31) == 0) sp[lane >> 5] = v;
    __syncthreads();
    if (lane == 0) out_loss[0] = -(sp[0] + sp[1]) / (float)B_;
}

// ---------------- launch ----------------

extern "C" void kernel_launch(void* const* d_in, const int* in_sizes, int n_in,
                              void* d_out, int out_size)
{
    const float* hs     = (const float*)d_in[0];
    const float* W      = (const float*)d_in[1];
    const float* bias   = (const float*)d_in[2];
    const float* trans  = (const float*)d_in[3];
    const float* startT = (const float*)d_in[4];
    const float* endT   = (const float*)d_in[5];
    const int*   att    = (const int*)d_in[6];
    const int*   labels = (const int*)d_in[7];
    float* out = (float*)d_out;

    const size_t smem = (size_t)(H_ * WPAD + NWARP * STRIDE_W) * sizeof(float);
    cudaFuncSetAttribute(gemm_kernel, cudaFuncAttributeMaxDynamicSharedMemorySize, (int)smem);

    gemm_kernel<<<GEMM_GRID, GNT, smem>>>(hs, W, bias, out);
    crf_kernel<<<B_, 128>>>(out, trans, startT, endT, att, labels);
    reduce_kernel<<<1, 64>>>(out + (out_size - 1));
}